// round 4
// baseline (speedup 1.0000x reference)
#include <cuda_runtime.h>

#define BB 8
#define TT 512
#define DD 512
#define VV 32000
#define FOURD 2048
#define NBLK 128

// ---------------- device scratch (no allocations allowed) ----------------
__device__ float g_x [BB*TT*DD];       // embedded (shifted) input
__device__ float g_xW[BB*TT*FOURD];    // x @ Wx + b precompute
__device__ float g_h1[BB*TT*DD];       // layer-0 hidden sequence
__device__ float g_h2[BB*TT*DD];       // layer-1 hidden sequence
__device__ int   g_cnt[2*TT];          // per-step release counters (2 layers)

// ---------------- f32x2 helpers (FFMA2: 2x fp32 throughput) ----------------
__device__ __forceinline__ unsigned long long pack2(float lo, float hi) {
    unsigned long long r;
    asm("mov.b64 %0, {%1, %2};" : "=l"(r) : "f"(lo), "f"(hi));
    return r;
}
__device__ __forceinline__ void fma2(unsigned long long &acc,
                                     unsigned long long a, unsigned long long b) {
    asm("fma.rn.f32x2 %0, %1, %2, %0;" : "+l"(acc) : "l"(a), "l"(b));
}
__device__ __forceinline__ float2 unpack2(unsigned long long v) {
    float2 f;
    asm("mov.b64 {%0, %1}, %2;" : "=f"(f.x), "=f"(f.y) : "l"(v));
    return f;
}

// ---------------- embedding + shift-right + counter reset ----------------
// NOTE: reference pads the TOKEN IDS with 0 and then embeds, so position t=0
// uses embed[0] (the embedding of token id 0), NOT a zero vector.
__global__ void __launch_bounds__(128) embed_kernel(
    const int* __restrict__ tokens, const float* __restrict__ emb,
    float* __restrict__ out)
{
    int row = blockIdx.x;          // row = b*T + t
    int t = row & (TT - 1);
    int tok = (t == 0) ? 0 : tokens[row - 1];   // shifted token (pad id = 0)
    float4 v = *(const float4*)(emb + (size_t)tok * DD + threadIdx.x * 4);
    *(float4*)(out + (size_t)row * DD + threadIdx.x * 4) = v;
    if (blockIdx.x == 0) {
        for (int i = threadIdx.x; i < 2*TT; i += 128) g_cnt[i] = 0;
    }
}

// ---------------- fp32 SGEMM with f32x2, 128x128x16 tiles, 8x8 thread tile ----------------
// C[M,N] = A[M,K] @ W[K,N] + bias[N].  M%128==0, N%128==0, K%16==0 (all exact here).
__global__ void __launch_bounds__(256) sgemm_f32x2(
    const float* __restrict__ A, const float* __restrict__ W,
    const float* __restrict__ bias, float* __restrict__ C,
    int M, int N, int K)
{
    __shared__ float As[16][132];   // padded to soften transpose-store conflicts
    __shared__ float Bs[16][128];

    const int tid  = threadIdx.x;
    const int trow = tid >> 4;      // 0..15 -> rows trow*8..+7
    const int tcol = tid & 15;      // 0..15 -> cols tcol*8..+7
    const int bx = blockIdx.x, by = blockIdx.y;

    unsigned long long acc[8][4];
    #pragma unroll
    for (int i = 0; i < 8; i++)
        #pragma unroll
        for (int j = 0; j < 4; j++) acc[i][j] = 0ull;

    const float* Ap = A + (size_t)(by * 128) * K;
    const float* Bp = W + (size_t)(bx * 128);

    for (int kt = 0; kt < K; kt += 16) {
        #pragma unroll
        for (int l = 0; l < 2; l++) {
            int idx = tid + l * 256;
            // A tile: 128 rows x 16 k, transposed store
            int r  = idx >> 2;
            int kv = (idx & 3) * 4;
            float4 a = *(const float4*)(Ap + (size_t)r * K + kt + kv);
            As[kv + 0][r] = a.x; As[kv + 1][r] = a.y;
            As[kv + 2][r] = a.z; As[kv + 3][r] = a.w;
            // B tile: 16 k x 128 cols, direct store
            int kr = idx >> 5;
            int cv = (idx & 31) * 4;
            *(float4*)&Bs[kr][cv] =
                *(const float4*)(Bp + (size_t)(kt + kr) * N + cv);
        }
        __syncthreads();
        #pragma unroll
        for (int k = 0; k < 16; k++) {
            float4 a0 = *(float4*)&As[k][trow * 8];
            float4 a1 = *(float4*)&As[k][trow * 8 + 4];
            ulonglong2 b0 = *(ulonglong2*)&Bs[k][tcol * 8];
            ulonglong2 b1 = *(ulonglong2*)&Bs[k][tcol * 8 + 4];
            unsigned long long bb[4] = { b0.x, b0.y, b1.x, b1.y };
            float av[8] = { a0.x, a0.y, a0.z, a0.w, a1.x, a1.y, a1.z, a1.w };
            #pragma unroll
            for (int i = 0; i < 8; i++) {
                unsigned long long a2 = pack2(av[i], av[i]);
                #pragma unroll
                for (int j = 0; j < 4; j++) fma2(acc[i][j], a2, bb[j]);
            }
        }
        __syncthreads();
    }

    // epilogue: + bias, store
    const int c0 = bx * 128 + tcol * 8;
    float bsv[8];
    #pragma unroll
    for (int j = 0; j < 8; j++) bsv[j] = bias[c0 + j];
    #pragma unroll
    for (int i = 0; i < 8; i++) {
        int r = by * 128 + trow * 8 + i;
        float ov[8];
        #pragma unroll
        for (int j = 0; j < 4; j++) {
            float2 f = unpack2(acc[i][j]);
            ov[2*j]   = f.x + bsv[2*j];
            ov[2*j+1] = f.y + bsv[2*j+1];
        }
        float* cp = C + (size_t)r * N + c0;
        *(float4*)(cp)     = make_float4(ov[0], ov[1], ov[2], ov[3]);
        *(float4*)(cp + 4) = make_float4(ov[4], ov[5], ov[6], ov[7]);
    }
}

// ---------------- persistent LSTM recurrence ----------------
// grid = 128 CTAs (one wave, all co-resident), 128 threads each.
// CTA blk owns h-dims {4*blk .. 4*blk+3} -> 16 gate columns (i,f,g,o x 4 dims).
// Wh slice (512x16) cached in SMEM once; h broadcast via global per step with
// per-step release counters.
__global__ void __launch_bounds__(128) lstm_kernel(
    const float* __restrict__ xW, const float* __restrict__ Wh,
    float* __restrict__ hseq, int cntBase)
{
    extern __shared__ char smem[];
    float (*w_s)[16] = (float(*)[16])smem;                                    // 32768 B
    unsigned long long (*h_d)[512] = (unsigned long long(*)[512])(smem + 32768); // 32768 B ((h,h) packed)
    float (*red)[128] = (float(*)[128])(smem + 65536);                        //  4096 B
    float* gs  = (float*)(smem + 69632);                                      //   512 B
    float* c_s = (float*)(smem + 70144);                                      //   128 B

    const int tid = threadIdx.x;
    const int blk = blockIdx.x;

    // load Wh slice: local col c -> global column (c>>2)*D + blk*4 + (c&3)
    for (int idx = tid; idx < 512 * 16; idx += 128) {
        int k = idx >> 4, c = idx & 15;
        int gcol = (c >> 2) * DD + blk * 4 + (c & 3);
        w_s[k][c] = Wh[(size_t)k * FOURD + gcol];
    }
    if (tid < 32) c_s[tid] = 0.f;
    __syncthreads();

    const int w    = tid >> 5;        // warp: k-quarter
    const int lane = tid & 31;
    const int kp = lane >> 4;         // k parity within quarter
    const int bq = (lane >> 2) & 3;   // b pair: {bq, bq+4}
    const int cq = lane & 3;          // col group: cols 4*cq..4*cq+3

    // fixed output mapping for the epilogue threads
    const int ob = tid >> 4, oc = tid & 15;
    const size_t xw_coloff = (size_t)((oc >> 2) * DD + blk * 4 + (oc & 3));

    for (int t = 0; t < TT; t++) {
        // prefetch this thread's xW early (no dependency on h)
        float xwv = xW[((size_t)(ob * TT + t)) * FOURD + xw_coloff];

        if (t > 0) {
            if (tid == 0) {
                volatile int* p = &g_cnt[cntBase + t - 1];
                while (*p < NBLK) { }
            }
            __threadfence();
            __syncthreads();
            // load h[t-1] into SMEM as duplicated (h,h) b64 pairs, layout [b][k]
            #pragma unroll
            for (int bb = 0; bb < 2; bb++) {
                int b = w * 2 + bb;
                const float* hp = hseq + ((size_t)(b * TT + t - 1)) * DD;
                #pragma unroll
                for (int j = 0; j < 8; j++) {
                    int k = j * 64 + lane * 2;
                    float2 hv = *(const float2*)(hp + k);
                    ulonglong2 pv;
                    pv.x = pack2(hv.x, hv.x);
                    pv.y = pack2(hv.y, hv.y);
                    *(ulonglong2*)&h_d[b][k] = pv;
                }
            }
            __syncthreads();
        }

        unsigned long long acc[2][2] = { {0ull, 0ull}, {0ull, 0ull} };
        if (t > 0) {
            const unsigned long long* h0 = h_d[bq];
            const unsigned long long* h1 = h_d[bq + 4];
            const int kbase = w * 128 + kp;
            #pragma unroll 8
            for (int i = 0; i < 64; i++) {
                int k = kbase + i * 2;
                ulonglong2 wv = *(const ulonglong2*)&w_s[k][cq * 4];
                unsigned long long hp0 = h0[k];
                unsigned long long hp1 = h1[k];
                fma2(acc[0][0], hp0, wv.x);
                fma2(acc[0][1], hp0, wv.y);
                fma2(acc[1][0], hp1, wv.x);
                fma2(acc[1][1], hp1, wv.y);
            }
        }

        // write partials: red[warp*2+kp][b*16 + c]
        {
            int rw = w * 2 + kp;
            #pragma unroll
            for (int bi = 0; bi < 2; bi++)
                #pragma unroll
                for (int pj = 0; pj < 2; pj++) {
                    int b  = bq + bi * 4;
                    int cb = cq * 4 + pj * 2;
                    *(unsigned long long*)&red[rw][b * 16 + cb] = acc[bi][pj];
                }
        }
        __syncthreads();

        // sum 8 partials + xW -> gate pre-activation
        {
            float s = 0.f;
            #pragma unroll
            for (int r = 0; r < 8; r++) s += red[r][tid];
            gs[tid] = s + xwv;
        }
        __syncthreads();

        if (tid < 32) {
            int b = tid >> 2, dd = tid & 3;
            float iv = gs[b * 16 + dd];
            float fv = gs[b * 16 + 4 + dd];
            float gv = gs[b * 16 + 8 + dd];
            float ov = gs[b * 16 + 12 + dd];
            float ig = 1.f / (1.f + __expf(-iv));
            float fg = 1.f / (1.f + __expf(-fv));
            float gg = tanhf(gv);
            float og = 1.f / (1.f + __expf(-ov));
            float cc = fg * c_s[tid] + ig * gg;
            c_s[tid] = cc;
            float hh = og * tanhf(cc);
            hseq[((size_t)(b * TT + t)) * DD + blk * 4 + dd] = hh;
        }
        __threadfence();
        __syncthreads();
        if (tid == 0) atomicAdd(&g_cnt[cntBase + t], 1);
    }
}

// ---------------- launch ----------------
extern "C" void kernel_launch(void* const* d_in, const int* in_sizes, int n_in,
                              void* d_out, int out_size)
{
    const int*   tokens = (const int*)d_in[0];
    const float* emb    = (const float*)d_in[1];
    const float* Wx0    = (const float*)d_in[2];
    const float* Wh0    = (const float*)d_in[3];
    const float* b0     = (const float*)d_in[4];
    const float* Wx1    = (const float*)d_in[5];
    const float* Wh1    = (const float*)d_in[6];
    const float* b1     = (const float*)d_in[7];
    const float* Wout   = (const float*)d_in[8];
    const float* bout   = (const float*)d_in[9];
    float* out = (float*)d_out;

    float *gx, *gxw, *gh1, *gh2;
    cudaGetSymbolAddress((void**)&gx,  g_x);
    cudaGetSymbolAddress((void**)&gxw, g_xW);
    cudaGetSymbolAddress((void**)&gh1, g_h1);
    cudaGetSymbolAddress((void**)&gh2, g_h2);

    const int lstm_smem = 70272;
    cudaFuncSetAttribute((const void*)lstm_kernel,
                         cudaFuncAttributeMaxDynamicSharedMemorySize, lstm_smem);

    // 1) embedding + shift (+ counter reset)
    embed_kernel<<<BB * TT, 128>>>(tokens, emb, gx);
    // 2) layer 0: xW = x @ Wx0 + b0
    sgemm_f32x2<<<dim3(FOURD / 128, (BB * TT) / 128), 256>>>(gx, Wx0, b0, gxw,
                                                             BB * TT, FOURD, DD);
    // 3) layer 0 recurrence
    lstm_kernel<<<NBLK, 128, lstm_smem>>>(gxw, Wh0, gh1, 0);
    // 4) layer 1: xW = h1 @ Wx1 + b1
    sgemm_f32x2<<<dim3(FOURD / 128, (BB * TT) / 128), 256>>>(gh1, Wx1, b1, gxw,
                                                             BB * TT, FOURD, DD);
    // 5) layer 1 recurrence
    lstm_kernel<<<NBLK, 128, lstm_smem>>>(gxw, Wh1, gh2, TT);
    // 6) logits = h2 @ Wout + bout
    sgemm_f32x2<<<dim3(VV / 128, (BB * TT) / 128), 256>>>(gh2, Wout, bout, out,
                                                          BB * TT, VV, DD);
}

// round 6
// speedup vs baseline: 1.3294x; 1.3294x over previous
#include <cuda_runtime.h>
#include <cstdint>

#define BB 8
#define TT 512
#define DD 512
#define VV 32000
#define FOURD 2048
#define NBLK 128

// ---------------- device scratch (no allocations allowed) ----------------
__device__ float g_x  [BB*TT*DD];       // embedded (shifted) input
__device__ float g_xW [BB*TT*FOURD];    // x @ Wx + b precompute
__device__ float g_h1 [BB*TT*DD];       // layer-0 hidden sequence
__device__ float g_h2 [BB*TT*DD];       // layer-1 hidden sequence
__device__ float g_h2r[BB*TT*DD];       // h2 rounded to tf32
__device__ float g_Wt [(size_t)VV*DD];  // Wout^T [V,512], tf32-rounded
__device__ int   g_cnt[2*TT];           // per-step release counters (2 layers)

// ---------------- f32x2 helpers (FFMA2: 2x fp32 throughput) ----------------
__device__ __forceinline__ unsigned long long pack2(float lo, float hi) {
    unsigned long long r;
    asm("mov.b64 %0, {%1, %2};" : "=l"(r) : "f"(lo), "f"(hi));
    return r;
}
__device__ __forceinline__ void fma2(unsigned long long &acc,
                                     unsigned long long a, unsigned long long b) {
    asm("fma.rn.f32x2 %0, %1, %2, %0;" : "+l"(acc) : "l"(a), "l"(b));
}
__device__ __forceinline__ float2 unpack2(unsigned long long v) {
    float2 f;
    asm("mov.b64 {%0, %1}, %2;" : "=f"(f.x), "=f"(f.y) : "l"(v));
    return f;
}

// ---------------- small helpers ----------------
__device__ __forceinline__ uint32_t smem_u32(const void* p) {
    uint32_t a;
    asm("{ .reg .u64 t; cvta.to.shared.u64 t, %1; cvt.u32.u64 %0, t; }"
        : "=r"(a) : "l"(p));
    return a;
}
__device__ __forceinline__ float tf32r(float x) {
    uint32_t r;
    asm("cvt.rna.tf32.f32 %0, %1;" : "=r"(r) : "f"(x));
    return __uint_as_float(r);
}
__device__ __forceinline__ void cp_async16(uint32_t dst, const void* src) {
    asm volatile("cp.async.ca.shared.global [%0], [%1], 16;"
                 :: "r"(dst), "l"(src) : "memory");
}
__device__ __forceinline__ void cp_commit() {
    asm volatile("cp.async.commit_group;" ::: "memory");
}
template<int N> __device__ __forceinline__ void cp_wait() {
    asm volatile("cp.async.wait_group %0;" :: "n"(N) : "memory");
}
// mma.sync tf32 m16n8k8 (portable PTX; HMMA on Blackwell)
__device__ __forceinline__ void mma_tf32(float* c, const uint32_t* a, const uint32_t* b) {
    asm volatile(
        "mma.sync.aligned.m16n8k8.row.col.f32.tf32.tf32.f32 "
        "{%0,%1,%2,%3}, {%4,%5,%6,%7}, {%8,%9}, {%0,%1,%2,%3};"
        : "+f"(c[0]), "+f"(c[1]), "+f"(c[2]), "+f"(c[3])
        : "r"(a[0]), "r"(a[1]), "r"(a[2]), "r"(a[3]), "r"(b[0]), "r"(b[1]));
}

// ---------------- embedding + shift-right + counter reset ----------------
// Reference pads TOKEN IDS with 0 then embeds: t=0 uses embed[0].
__global__ void __launch_bounds__(128) embed_kernel(
    const int* __restrict__ tokens, const float* __restrict__ emb,
    float* __restrict__ out)
{
    int row = blockIdx.x;          // row = b*T + t
    int t = row & (TT - 1);
    int tok = (t == 0) ? 0 : tokens[row - 1];
    float4 v = *(const float4*)(emb + (size_t)tok * DD + threadIdx.x * 4);
    *(float4*)(out + (size_t)row * DD + threadIdx.x * 4) = v;
    if (blockIdx.x == 0) {
        for (int i = threadIdx.x; i < 2*TT; i += 128) g_cnt[i] = 0;
    }
}

// ---------------- transpose + tf32-round Wout [512,32000] -> Wt [32000,512] ----------------
__global__ void __launch_bounds__(256) transpose_round_kernel(
    const float* __restrict__ W, float* __restrict__ Wt)
{
    __shared__ float tile[32][33];
    int n0 = blockIdx.x * 32, k0 = blockIdx.y * 32;
    int tx = threadIdx.x & 31, ty = threadIdx.x >> 5;  // 32 x 8
    #pragma unroll
    for (int j = 0; j < 4; j++)
        tile[ty + j*8][tx] = W[(size_t)(k0 + ty + j*8) * VV + n0 + tx];
    __syncthreads();
    #pragma unroll
    for (int j = 0; j < 4; j++)
        Wt[(size_t)(n0 + ty + j*8) * DD + k0 + tx] = tf32r(tile[tx][ty + j*8]);
}

// ---------------- elementwise tf32 round: h2 -> h2r ----------------
__global__ void __launch_bounds__(256) round_tf32_kernel(
    const float* __restrict__ in, float* __restrict__ out)
{
    int i = blockIdx.x * 256 + threadIdx.x;     // float4 index
    float4 v = ((const float4*)in)[i];
    v.x = tf32r(v.x); v.y = tf32r(v.y); v.z = tf32r(v.z); v.w = tf32r(v.w);
    ((float4*)out)[i] = v;
}

// ---------------- tf32 mma.sync GEMM: C[4096,32000] = A @ Bt^T + bias ----------------
// A [4096,512] row-major (tf32-rounded), Bt [32000,512] row-major (= col-major B).
// Tile 128M x 128N, K staged by 32, cp.async double buffer.
// SMEM per stage: As[128][36] + Bs[128][36] floats = 36864 B; 2 stages = 73728 B.
#define GSTAGE_B 36864
#define GEMM_SMEM (2*GSTAGE_B)

__global__ void __launch_bounds__(256) gemm_mma_kernel(
    const float* __restrict__ A, const float* __restrict__ Bt,
    const float* __restrict__ bias, float* __restrict__ C)
{
    extern __shared__ char smem[];
    const int tid  = threadIdx.x;
    const int wid  = tid >> 5;
    const int lane = tid & 31;
    const int bx = blockIdx.x, by = blockIdx.y;
    const uint32_t sb = smem_u32(smem);

    const int m0 = (wid >> 2) * 64;   // warp M offset in tile
    const int n0 = (wid & 3) * 32;    // warp N offset in tile
    const int fr = lane >> 2;         // fragment row/group
    const int fc = lane & 3;          // fragment col/thread-in-group

    const float* Asrc = A  + (size_t)(by * 128) * DD;
    const float* Bsrc = Bt + (size_t)(bx * 128) * DD;

    // per-thread load slots: 4 float4 per operand per stage
    int lr[4], lc[4];
    #pragma unroll
    for (int i = 0; i < 4; i++) {
        int idx = tid + i * 256;     // 0..1023
        lr[i] = idx >> 3;            // row 0..127
        lc[i] = (idx & 7) * 4;       // col 0,4,..,28
    }

    // prologue: stages 0,1
    #pragma unroll
    for (int s = 0; s < 2; s++) {
        uint32_t base = sb + s * GSTAGE_B;
        #pragma unroll
        for (int i = 0; i < 4; i++) {
            uint32_t doff = (uint32_t)(lr[i] * 36 + lc[i]) * 4;
            cp_async16(base + doff,             Asrc + (size_t)lr[i] * DD + s * 32 + lc[i]);
            cp_async16(base + 18432 + doff,     Bsrc + (size_t)lr[i] * DD + s * 32 + lc[i]);
        }
        cp_commit();
    }

    float acc[4][4][4];
    #pragma unroll
    for (int mt = 0; mt < 4; mt++)
        #pragma unroll
        for (int nt = 0; nt < 4; nt++)
            #pragma unroll
            for (int j = 0; j < 4; j++) acc[mt][nt][j] = 0.f;

    for (int s = 0; s < 16; s++) {
        if (s < 15) cp_wait<1>(); else cp_wait<0>();
        __syncthreads();

        const uint32_t* Au = (const uint32_t*)(smem + (s & 1) * GSTAGE_B);
        const uint32_t* Bu = Au + 4608;   // 18432 B / 4

        #pragma unroll
        for (int kb = 0; kb < 4; kb++) {
            const int kc = kb * 8;
            uint32_t af[4][4], bf[4][2];
            #pragma unroll
            for (int mt = 0; mt < 4; mt++) {
                const uint32_t* ap = Au + (m0 + mt * 16 + fr) * 36 + kc + fc;
                af[mt][0] = ap[0];
                af[mt][1] = ap[8 * 36];
                af[mt][2] = ap[4];
                af[mt][3] = ap[8 * 36 + 4];
            }
            #pragma unroll
            for (int nt = 0; nt < 4; nt++) {
                const uint32_t* bp = Bu + (n0 + nt * 8 + fr) * 36 + kc + fc;
                bf[nt][0] = bp[0];
                bf[nt][1] = bp[4];
            }
            #pragma unroll
            for (int mt = 0; mt < 4; mt++)
                #pragma unroll
                for (int nt = 0; nt < 4; nt++)
                    mma_tf32(acc[mt][nt], af[mt], bf[nt]);
        }
        __syncthreads();

        if (s + 2 < 16) {
            uint32_t base = sb + (s & 1) * GSTAGE_B;
            const int k0 = (s + 2) * 32;
            #pragma unroll
            for (int i = 0; i < 4; i++) {
                uint32_t doff = (uint32_t)(lr[i] * 36 + lc[i]) * 4;
                cp_async16(base + doff,         Asrc + (size_t)lr[i] * DD + k0 + lc[i]);
                cp_async16(base + 18432 + doff, Bsrc + (size_t)lr[i] * DD + k0 + lc[i]);
            }
            cp_commit();
        }
    }

    // epilogue: c0,c1 -> (row, 2fc..2fc+1); c2,c3 -> (row+8, same cols)
    const int colbase = bx * 128 + n0;
    float2 bv[4];
    #pragma unroll
    for (int nt = 0; nt < 4; nt++)
        bv[nt] = *(const float2*)&bias[colbase + nt * 8 + 2 * fc];
    #pragma unroll
    for (int mt = 0; mt < 4; mt++) {
        const size_t r0 = (size_t)(by * 128 + m0 + mt * 16 + fr);
        #pragma unroll
        for (int nt = 0; nt < 4; nt++) {
            const size_t coff = (size_t)(colbase + nt * 8 + 2 * fc);
            float2 v0 = make_float2(acc[mt][nt][0] + bv[nt].x,
                                    acc[mt][nt][1] + bv[nt].y);
            float2 v1 = make_float2(acc[mt][nt][2] + bv[nt].x,
                                    acc[mt][nt][3] + bv[nt].y);
            *(float2*)(C + r0 * VV + coff)       = v0;
            *(float2*)(C + (r0 + 8) * VV + coff) = v1;
        }
    }
}

// ---------------- fp32 SGEMM with f32x2 (input GEMMs) ----------------
__global__ void __launch_bounds__(256) sgemm_f32x2(
    const float* __restrict__ A, const float* __restrict__ W,
    const float* __restrict__ bias, float* __restrict__ C,
    int M, int N, int K)
{
    __shared__ float As[16][132];
    __shared__ float Bs[16][128];

    const int tid  = threadIdx.x;
    const int trow = tid >> 4;
    const int tcol = tid & 15;
    const int bx = blockIdx.x, by = blockIdx.y;

    unsigned long long acc[8][4];
    #pragma unroll
    for (int i = 0; i < 8; i++)
        #pragma unroll
        for (int j = 0; j < 4; j++) acc[i][j] = 0ull;

    const float* Ap = A + (size_t)(by * 128) * K;
    const float* Bp = W + (size_t)(bx * 128);

    for (int kt = 0; kt < K; kt += 16) {
        #pragma unroll
        for (int l = 0; l < 2; l++) {
            int idx = tid + l * 256;
            int r  = idx >> 2;
            int kv = (idx & 3) * 4;
            float4 a = *(const float4*)(Ap + (size_t)r * K + kt + kv);
            As[kv + 0][r] = a.x; As[kv + 1][r] = a.y;
            As[kv + 2][r] = a.z; As[kv + 3][r] = a.w;
            int kr = idx >> 5;
            int cv = (idx & 31) * 4;
            *(float4*)&Bs[kr][cv] =
                *(const float4*)(Bp + (size_t)(kt + kr) * N + cv);
        }
        __syncthreads();
        #pragma unroll
        for (int k = 0; k < 16; k++) {
            float4 a0 = *(float4*)&As[k][trow * 8];
            float4 a1 = *(float4*)&As[k][trow * 8 + 4];
            ulonglong2 b0 = *(ulonglong2*)&Bs[k][tcol * 8];
            ulonglong2 b1 = *(ulonglong2*)&Bs[k][tcol * 8 + 4];
            unsigned long long bb[4] = { b0.x, b0.y, b1.x, b1.y };
            float av[8] = { a0.x, a0.y, a0.z, a0.w, a1.x, a1.y, a1.z, a1.w };
            #pragma unroll
            for (int i = 0; i < 8; i++) {
                unsigned long long a2 = pack2(av[i], av[i]);
                #pragma unroll
                for (int j = 0; j < 4; j++) fma2(acc[i][j], a2, bb[j]);
            }
        }
        __syncthreads();
    }

    const int c0 = bx * 128 + tcol * 8;
    float bsv[8];
    #pragma unroll
    for (int j = 0; j < 8; j++) bsv[j] = bias[c0 + j];
    #pragma unroll
    for (int i = 0; i < 8; i++) {
        int r = by * 128 + trow * 8 + i;
        float ov[8];
        #pragma unroll
        for (int j = 0; j < 4; j++) {
            float2 f = unpack2(acc[i][j]);
            ov[2*j]   = f.x + bsv[2*j];
            ov[2*j+1] = f.y + bsv[2*j+1];
        }
        float* cp = C + (size_t)r * N + c0;
        *(float4*)(cp)     = make_float4(ov[0], ov[1], ov[2], ov[3]);
        *(float4*)(cp + 4) = make_float4(ov[4], ov[5], ov[6], ov[7]);
    }
}

// ---------------- persistent LSTM recurrence ----------------
__global__ void __launch_bounds__(128) lstm_kernel(
    const float* __restrict__ xW, const float* __restrict__ Wh,
    float* __restrict__ hseq, int cntBase)
{
    extern __shared__ char smem[];
    float (*w_s)[16] = (float(*)[16])smem;                                    // 32768 B
    unsigned long long (*h_d)[512] = (unsigned long long(*)[512])(smem + 32768); // 32768 B
    float (*red)[128] = (float(*)[128])(smem + 65536);                        //  4096 B
    float* gs  = (float*)(smem + 69632);                                      //   512 B
    float* c_s = (float*)(smem + 70144);                                      //   128 B

    const int tid = threadIdx.x;
    const int blk = blockIdx.x;

    for (int idx = tid; idx < 512 * 16; idx += 128) {
        int k = idx >> 4, c = idx & 15;
        int gcol = (c >> 2) * DD + blk * 4 + (c & 3);
        w_s[k][c] = Wh[(size_t)k * FOURD + gcol];
    }
    if (tid < 32) c_s[tid] = 0.f;
    __syncthreads();

    const int w    = tid >> 5;
    const int lane = tid & 31;
    const int kp = lane >> 4;
    const int bq = (lane >> 2) & 3;
    const int cq = lane & 3;

    const int ob = tid >> 4, oc = tid & 15;
    const size_t xw_coloff = (size_t)((oc >> 2) * DD + blk * 4 + (oc & 3));

    for (int t = 0; t < TT; t++) {
        float xwv = xW[((size_t)(ob * TT + t)) * FOURD + xw_coloff];

        if (t > 0) {
            if (tid == 0) {
                volatile int* p = &g_cnt[cntBase + t - 1];
                while (*p < NBLK) { }
            }
            __threadfence();
            __syncthreads();
            #pragma unroll
            for (int bb = 0; bb < 2; bb++) {
                int b = w * 2 + bb;
                const float* hp = hseq + ((size_t)(b * TT + t - 1)) * DD;
                #pragma unroll
                for (int j = 0; j < 8; j++) {
                    int k = j * 64 + lane * 2;
                    float2 hv = *(const float2*)(hp + k);
                    ulonglong2 pv;
                    pv.x = pack2(hv.x, hv.x);
                    pv.y = pack2(hv.y, hv.y);
                    *(ulonglong2*)&h_d[b][k] = pv;
                }
            }
            __syncthreads();
        }

        unsigned long long acc[2][2] = { {0ull, 0ull}, {0ull, 0ull} };
        if (t > 0) {
            const unsigned long long* h0 = h_d[bq];
            const unsigned long long* h1 = h_d[bq + 4];
            const int kbase = w * 128 + kp;
            #pragma unroll 8
            for (int i = 0; i < 64; i++) {
                int k = kbase + i * 2;
                ulonglong2 wv = *(const ulonglong2*)&w_s[k][cq * 4];
                unsigned long long hp0 = h0[k];
                unsigned long long hp1 = h1[k];
                fma2(acc[0][0], hp0, wv.x);
                fma2(acc[0][1], hp0, wv.y);
                fma2(acc[1][0], hp1, wv.x);
                fma2(acc[1][1], hp1, wv.y);
            }
        }

        {
            int rw = w * 2 + kp;
            #pragma unroll
            for (int bi = 0; bi < 2; bi++)
                #pragma unroll
                for (int pj = 0; pj < 2; pj++) {
                    int b  = bq + bi * 4;
                    int cb = cq * 4 + pj * 2;
                    *(unsigned long long*)&red[rw][b * 16 + cb] = acc[bi][pj];
                }
        }
        __syncthreads();

        {
            float s = 0.f;
            #pragma unroll
            for (int r = 0; r < 8; r++) s += red[r][tid];
            gs[tid] = s + xwv;
        }
        __syncthreads();

        if (tid < 32) {
            int b = tid >> 2, dd = tid & 3;
            float iv = gs[b * 16 + dd];
            float fv = gs[b * 16 + 4 + dd];
            float gv = gs[b * 16 + 8 + dd];
            float ov = gs[b * 16 + 12 + dd];
            float ig = 1.f / (1.f + __expf(-iv));
            float fg = 1.f / (1.f + __expf(-fv));
            float gg = tanhf(gv);
            float og = 1.f / (1.f + __expf(-ov));
            float cc = fg * c_s[tid] + ig * gg;
            c_s[tid] = cc;
            float hh = og * tanhf(cc);
            hseq[((size_t)(b * TT + t)) * DD + blk * 4 + dd] = hh;
        }
        __threadfence();
        __syncthreads();
        if (tid == 0) atomicAdd(&g_cnt[cntBase + t], 1);
    }
}

// ---------------- launch ----------------
extern "C" void kernel_launch(void* const* d_in, const int* in_sizes, int n_in,
                              void* d_out, int out_size)
{
    const int*   tokens = (const int*)d_in[0];
    const float* emb    = (const float*)d_in[1];
    const float* Wx0    = (const float*)d_in[2];
    const float* Wh0    = (const float*)d_in[3];
    const float* b0     = (const float*)d_in[4];
    const float* Wx1    = (const float*)d_in[5];
    const float* Wh1    = (const float*)d_in[6];
    const float* b1     = (const float*)d_in[7];
    const float* Wout   = (const float*)d_in[8];
    const float* bout   = (const float*)d_in[9];
    float* out = (float*)d_out;

    float *gx, *gxw, *gh1, *gh2, *gh2r, *gwt;
    cudaGetSymbolAddress((void**)&gx,   g_x);
    cudaGetSymbolAddress((void**)&gxw,  g_xW);
    cudaGetSymbolAddress((void**)&gh1,  g_h1);
    cudaGetSymbolAddress((void**)&gh2,  g_h2);
    cudaGetSymbolAddress((void**)&gh2r, g_h2r);
    cudaGetSymbolAddress((void**)&gwt,  g_Wt);

    const int lstm_smem = 70272;
    cudaFuncSetAttribute((const void*)lstm_kernel,
                         cudaFuncAttributeMaxDynamicSharedMemorySize, lstm_smem);
    cudaFuncSetAttribute((const void*)gemm_mma_kernel,
                         cudaFuncAttributeMaxDynamicSharedMemorySize, GEMM_SMEM);

    // 0) transpose+round Wout -> Wt [V,512]
    transpose_round_kernel<<<dim3(VV / 32, DD / 32), 256>>>(Wout, gwt);
    // 1) embedding + shift (+ counter reset)
    embed_kernel<<<BB * TT, 128>>>(tokens, emb, gx);
    // 2) layer 0: xW = x @ Wx0 + b0
    sgemm_f32x2<<<dim3(FOURD / 128, (BB * TT) / 128), 256>>>(gx, Wx0, b0, gxw,
                                                             BB * TT, FOURD, DD);
    // 3) layer 0 recurrence
    lstm_kernel<<<NBLK, 128, lstm_smem>>>(gxw, Wh0, gh1, 0);
    // 4) layer 1: xW = h1 @ Wx1 + b1
    sgemm_f32x2<<<dim3(FOURD / 128, (BB * TT) / 128), 256>>>(gh1, Wx1, b1, gxw,
                                                             BB * TT, FOURD, DD);
    // 5) layer 1 recurrence
    lstm_kernel<<<NBLK, 128, lstm_smem>>>(gxw, Wh1, gh2, TT);
    // 6) round h2 -> tf32
    round_tf32_kernel<<<(BB * TT * DD / 4) / 256, 256>>>(gh2, gh2r);
    // 7) logits = h2 @ Wout + bout via mma.sync tf32
    gemm_mma_kernel<<<dim3(VV / 128, (BB * TT) / 128), 256, GEMM_SMEM>>>(
        gh2r, gwt, bout, out);
}